// round 11
// baseline (speedup 1.0000x reference)
#include <cuda_runtime.h>
#include <cuda_fp16.h>

#define N_NODES 50000
#define N_EDGES 1600000
#define NB 10                // 128-edge batches per CTA (grid = 1.6M/1280 = 1250)

// Per-node precomputed readout vectors (one 128B line per node).
__device__ __align__(128) float g_prep[N_NODES * 32];
// L1 k8 frags: 8 frags x 32 lanes (uint = half2)
__device__ __align__(16) unsigned g_wfrags1[256];
// L2/L3/L4 k16 frags: 72 frags x 32 lanes (uint2)
__device__ __align__(16) uint2 g_wfrags2[2304];

// ---- SMEM layout (4-byte word offsets) ----
#define H2S     136          // row stride; 136 mod 32 == 8 -> conflict-free
#define WF1_OFF 0            // 256 words
#define WF2_OFF 256          // 4608 words
#define HP_OFF  4864         // 32 pair-rows x 136
#define CS_OFF  9216         // 16 rows x 136
#define SMEM_WORDS 11392
#define SMEM_BYTES (SMEM_WORDS * 4)   // 45568 B -> 4 CTAs/SM

// frag bases inside wf2 (units of frags = 32 uint2)
#define FB_L2 0
#define FB_L3 32
#define FB_L4 64

__device__ __forceinline__ unsigned h2bits(__half2 h) { return *(unsigned*)&h; }

// silu via HW tanh, fully fp16x2: silu(x) = h + h*tanh(h), h = x/2.
__device__ __forceinline__ unsigned silu_h2(float x0, float x1) {
    __half2 h = __floats2half2_rn(x0, x1);
    __half2 hh = __hmul2(h, __floats2half2_rn(0.5f, 0.5f));
    unsigned t;
    asm("tanh.approx.f16x2 %0, %1;" : "=r"(t) : "r"(h2bits(hh)));
    __half2 r = __hfma2(hh, *(__half2*)&t, hh);
    return h2bits(r);
}

__device__ __forceinline__ void mma_f16(float* d, unsigned a0, unsigned a1,
                                        unsigned a2, unsigned a3,
                                        unsigned b0, unsigned b1) {
    asm volatile(
        "mma.sync.aligned.m16n8k16.row.col.f32.f16.f16.f32 "
        "{%0,%1,%2,%3}, {%4,%5,%6,%7}, {%8,%9}, {%0,%1,%2,%3};"
        : "+f"(d[0]), "+f"(d[1]), "+f"(d[2]), "+f"(d[3])
        : "r"(a0), "r"(a1), "r"(a2), "r"(a3), "r"(b0), "r"(b1));
}

__device__ __forceinline__ void mma_f16_k8(float* d, unsigned a0, unsigned a1, unsigned b0) {
    asm volatile(
        "mma.sync.aligned.m16n8k8.row.col.f32.f16.f16.f32 "
        "{%0,%1,%2,%3}, {%4,%5}, {%6}, {%0,%1,%2,%3};"
        : "+f"(d[0]), "+f"(d[1]), "+f"(d[2]), "+f"(d[3])
        : "r"(a0), "r"(a1), "r"(b0));
}

__device__ __forceinline__ void red1(float* a, float v) {
    asm volatile("red.global.add.f32 [%0], %1;" :: "l"(a), "f"(v) : "memory");
}

// ============================================================================
// Setup kernel: per-node prep rows + out zeroing (all blocks) + weight frag
// packing (blocks 0..9). One launch; edge_kernel is the only other launch.
// ============================================================================
__global__ void __launch_bounds__(256)
setup_kernel(const float* __restrict__ nf,   // node_feats [N,256]
             const float* __restrict__ W0,   // [8,64]
             const float* __restrict__ W1,   // [8,64]
             const float* __restrict__ w1, const float* __restrict__ w2,
             const float* __restrict__ w3, const float* __restrict__ w4,
             float* __restrict__ out)
{
    const int tid = threadIdx.x;
    const float s8 = 0.3535533905932738f, s64 = 0.125f;

    // ---- weight frag packing (blocks 0..9) ----
    int idx = blockIdx.x * 256 + tid;
    if (idx < 256) {
        int f = idx >> 5, lane = idx & 31;
        int c = lane & 3, g = lane >> 2;
        int n = f * 8 + g;
        __half2 p = __floats2half2_rn(w1[(2*c) * 64 + n] * s8,
                                      w1[(2*c + 1) * 64 + n] * s8);
        g_wfrags1[idx] = h2bits(p);
    } else if (idx < 2560) {
        int t = idx - 256;
        int f = t >> 5, lane = t & 31;
        int c = lane & 3, g = lane >> 2;
        const float* w; int ncols, NT, fl;
        if (f < 32)      { w = w2; ncols = 64; NT = 8; fl = f; }
        else if (f < 64) { w = w3; ncols = 64; NT = 8; fl = f - 32; }
        else             { w = w4; ncols = 16; NT = 2; fl = f - 64; }
        int kt = fl / NT, nt = fl - kt * NT;
        int n = nt * 8 + g, kb = kt * 16 + 2 * c;
        __half2 x = __floats2half2_rn(w[kb * ncols + n] * s64,
                                      w[(kb + 1) * ncols + n] * s64);
        __half2 y = __floats2half2_rn(w[(kb + 8) * ncols + n] * s64,
                                      w[(kb + 9) * ncols + n] * s64);
        g_wfrags2[t] = make_uint2(h2bits(x), h2bits(y));
    }

    // ---- per-node prep (warp per node) ----
    __shared__ float sW0[512], sW1[512];
    for (int i = tid; i < 512; i += 256) { sW0[i] = W0[i]; sW1[i] = W1[i]; }
    __syncthreads();

    const int warp = tid >> 5;
    const int lane = tid & 31;
    const int n = blockIdx.x * 8 + warp;
    if (n >= N_NODES) return;

    const float* nrow = nf + (size_t)n * 256;
    const int v1 = lane, v2 = lane + 32;
    float x1 = nrow[v1], x2 = nrow[v2];
    float y1[3], y2[3];
    #pragma unroll
    for (int k = 0; k < 3; k++) {
        y1[k] = nrow[64 + v1 * 3 + k];
        y2[k] = nrow[64 + v2 * 3 + k];
    }

    float P[32];
    #pragma unroll
    for (int u = 0; u < 8; u++)
        P[u] = fmaf(sW0[u * 64 + v1], x1, sW0[u * 64 + v2] * x2);
    #pragma unroll
    for (int u = 0; u < 8; u++) {
        float wa = sW1[u * 64 + v1], wb = sW1[u * 64 + v2];
        #pragma unroll
        for (int k = 0; k < 3; k++)
            P[8 + u * 3 + k] = fmaf(wa, y1[k], wb * y2[k]);
    }

    #pragma unroll
    for (int off = 16; off; off >>= 1) {
        #pragma unroll
        for (int j = 0; j < 32; j++)
            P[j] += __shfl_xor_sync(0xffffffffu, P[j], off);
    }

    if (lane == 0) {
        const float c0 = 0.03125f;                        // 1/sqrt(8*64*2)
        const float c1 = 0.03125f * 0.5773502691896258f;  // c/sqrt(3)
        float* dst = g_prep + (size_t)n * 32;
        #pragma unroll
        for (int j = 0; j < 8; j++)  dst[j] = P[j] * c0;
        #pragma unroll
        for (int j = 8; j < 32; j++) dst[j] = P[j] * c1;
        out[n] = 0.f;                                     // zero accumulator
    }
}

// k16 layer: warp computes 16 edges x NT*8 outputs over KT*16 K.
template<int KT, int NT>
__device__ __forceinline__ void mma_layer(const uint2* __restrict__ wf,
                                          const unsigned* __restrict__ hp,
                                          int m0, int lane, float acc[][4]) {
    const int c = lane & 3, g = lane >> 2;
    #pragma unroll
    for (int kt = 0; kt < KT; kt++) {
        unsigned a0 = hp[(kt * 8 + c)     * H2S + m0 + g];
        unsigned a1 = hp[(kt * 8 + c)     * H2S + m0 + g + 8];
        unsigned a2 = hp[(kt * 8 + c + 4) * H2S + m0 + g];
        unsigned a3 = hp[(kt * 8 + c + 4) * H2S + m0 + g + 8];
        #pragma unroll
        for (int nt = 0; nt < NT; nt++) {
            uint2 b = wf[(kt * NT + nt) * 32 + lane];
            mma_f16(acc[nt], a0, a1, a2, a3, b.x, b.y);
        }
    }
}

// NOTE: no lead syncwarp — mma.sync is warp-convergent and has consumed every
// lane's A-register reads, so all hp loads of this layer are complete before
// any lane reaches the stores below.
template<int NT>
__device__ __forceinline__ void store_acts_h(unsigned* hp, int m0, int lane,
                                             float acc[][4]) {
    const int c = lane & 3, g = lane >> 2;
    #pragma unroll
    for (int nt = 0; nt < NT; nt++) {
        hp[(nt * 4 + c) * H2S + m0 + g]     = silu_h2(acc[nt][0], acc[nt][1]);
        hp[(nt * 4 + c) * H2S + m0 + g + 8] = silu_h2(acc[nt][2], acc[nt][3]);
    }
    __syncwarp();   // stores visible before next layer's loads
}

__global__ void __launch_bounds__(256, 4)
edge_kernel(const float* __restrict__ ef,   // edge_feats [E,8]
            const float* __restrict__ ea,   // edge_attrs [E,4]
            const float* __restrict__ qi,   // charges_induced [N,8]
            const int*   __restrict__ eidx, // edge_index [2,E]
            float* __restrict__ out)
{
    extern __shared__ float smem[];
    unsigned* wf1 = (unsigned*)smem;
    uint2*    wf2 = (uint2*)(smem + WF2_OFF);
    unsigned* hp  = (unsigned*)(smem + HP_OFF);
    float*    csm = smem + CS_OFF;

    const int tid  = threadIdx.x;
    const int lane = tid & 31;
    const int m0   = (tid >> 5) * 16;
    const int half = lane & 1;
    const int cm   = m0 + (lane >> 1);   // this lane's edge column
    const int c    = lane & 3;
    const int g    = lane >> 2;

    // Weight frags -> SMEM (block-cooperative; the only block sync).
    {
        const float4* s1 = (const float4*)g_wfrags1;   // 64 float4
        float4* d1 = (float4*)smem;
        if (tid < 64) d1[tid] = s1[tid];
        const float4* s2 = (const float4*)g_wfrags2;   // 1152 float4
        float4* d2 = (float4*)(smem + WF2_OFF);
        #pragma unroll
        for (int i = 0; i < 4; i++) d2[tid + i * 256] = s2[tid + i * 256];
        if (tid < 128) d2[tid + 1024] = s2[tid + 1024];
    }
    __syncthreads();

    const int ebase = blockIdx.x * (128 * NB);

    // Prefetch batch 0's indices (breaks the eidx -> qi/prep chain).
    int s_n = eidx[ebase + cm];
    int r_n = eidx[N_EDGES + ebase + cm];

    float acc[8][4];
    #define ZACC(N) { _Pragma("unroll") for (int i = 0; i < N; i++) { \
        acc[i][0]=0.f; acc[i][1]=0.f; acc[i][2]=0.f; acc[i][3]=0.f; } }

    #pragma unroll 1
    for (int b = 0; b < NB; b++) {
        const int s_ = s_n;
        const int r_ = r_n;
        const int me = ebase + b * 128 + cm;

        // ---- Single parallel LDG round ----
        float4 at = *(const float4*)(ea + (size_t)me * 4);
        float4 f4 = *(const float4*)(ef + (size_t)me * 8 + half * 4);
        float4 q0 = *(const float4*)(qi + (size_t)s_ * 8);
        float4 q1 = *(const float4*)(qi + (size_t)s_ * 8 + 4);
        const float4* pr = (const float4*)(g_prep + (size_t)r_ * 32);

        // Prefetch next batch's indices.
        if (b + 1 < NB) {
            s_n = eidx[ebase + (b + 1) * 128 + cm];
            r_n = eidx[N_EDGES + ebase + (b + 1) * 128 + cm];
        }

        // Stage layer-1 inputs.
        hp[(2 * half)     * H2S + cm] = h2bits(__floats2half2_rn(f4.x, f4.y));
        hp[(2 * half + 1) * H2S + cm] = h2bits(__floats2half2_rn(f4.z, f4.w));

        // Contract gather into csm[16][edge].
        float q[8] = {q0.x, q0.y, q0.z, q0.w, q1.x, q1.y, q1.z, q1.w};
        if (half == 0) {
            float4 Aa = pr[0], Ab = pr[1];
            float A0[8] = {Aa.x, Aa.y, Aa.z, Aa.w, Ab.x, Ab.y, Ab.z, Ab.w};
            #pragma unroll
            for (int u = 0; u < 8; u++) csm[u * H2S + cm] = (q[u] * at.x) * A0[u];
        } else {
            float A1[24];
            #pragma unroll
            for (int i = 0; i < 6; i++) {
                float4 v = pr[2 + i];
                A1[4*i] = v.x; A1[4*i+1] = v.y; A1[4*i+2] = v.z; A1[4*i+3] = v.w;
            }
            #pragma unroll
            for (int u = 0; u < 8; u++) {
                float bs = at.y * A1[3*u];
                bs = fmaf(at.z, A1[3*u + 1], bs);
                bs = fmaf(at.w, A1[3*u + 2], bs);
                csm[(8 + u) * H2S + cm] = q[u] * bs;
            }
        }
        __syncwarp();

        // ---- Layer 1: 8 -> 64 (k8) ----
        ZACC(8);
        {
            unsigned a0 = hp[c * H2S + m0 + g];
            unsigned a1 = hp[c * H2S + m0 + g + 8];
            #pragma unroll
            for (int nt = 0; nt < 8; nt++)
                mma_f16_k8(acc[nt], a0, a1, wf1[nt * 32 + lane]);
        }
        store_acts_h<8>(hp, m0, lane, acc);

        ZACC(8); mma_layer<4, 8>(wf2 + FB_L2 * 32, hp, m0, lane, acc);
        store_acts_h<8>(hp, m0, lane, acc);

        ZACC(8); mma_layer<4, 8>(wf2 + FB_L3 * 32, hp, m0, lane, acc);
        store_acts_h<8>(hp, m0, lane, acc);

        // ---- Layer 4: 64 -> 16, tail directly in D-fragment domain ----
        ZACC(2); mma_layer<4, 2>(wf2 + FB_L4 * 32, hp, m0, lane, acc);

        // Thread (g,c) holds tp rows {g, g+8} x cols {nt*8+2c, nt*8+2c+1}.
        float sA = 0.f, sB = 0.f;
        #pragma unroll
        for (int nt = 0; nt < 2; nt++) {
            const float* cr0 = csm + (nt * 8 + 2 * c) * H2S + m0;
            const float* cr1 = cr0 + H2S;
            sA = fmaf(acc[nt][0], cr0[g],     sA);
            sA = fmaf(acc[nt][1], cr1[g],     sA);
            sB = fmaf(acc[nt][2], cr0[g + 8], sB);
            sB = fmaf(acc[nt][3], cr1[g + 8], sB);
        }
        sA += __shfl_xor_sync(0xffffffffu, sA, 1);
        sA += __shfl_xor_sync(0xffffffffu, sA, 2);
        sB += __shfl_xor_sync(0xffffffffu, sB, 1);
        sB += __shfl_xor_sync(0xffffffffu, sB, 2);
        int rg  = __shfl_sync(0xffffffffu, r_, 2 * g);
        int rg8 = __shfl_sync(0xffffffffu, r_, 2 * g + 16);
        if (c == 0) {
            red1(out + rg,  sA);
            red1(out + rg8, sB);
        }
        __syncwarp();   // tail csm/hp reads done before next batch overwrites
    }
}

extern "C" void kernel_launch(void* const* d_in, const int* in_sizes, int n_in,
                              void* d_out, int out_size)
{
    const float* node_feats      = (const float*)d_in[0];
    const float* charges_induced = (const float*)d_in[2];
    const float* edge_feats      = (const float*)d_in[3];
    const float* edge_attrs      = (const float*)d_in[4];
    const float* mlp_w1          = (const float*)d_in[6];
    const float* mlp_w2          = (const float*)d_in[7];
    const float* mlp_w3          = (const float*)d_in[8];
    const float* mlp_w4          = (const float*)d_in[9];
    const float* W0              = (const float*)d_in[10];
    const float* W1              = (const float*)d_in[11];
    const int*   eidx            = (const int*)d_in[12];
    float* out = (float*)d_out;

    setup_kernel<<<(N_NODES + 7) / 8, 256>>>(node_feats, W0, W1,
                                             mlp_w1, mlp_w2, mlp_w3, mlp_w4, out);

    cudaFuncSetAttribute(edge_kernel, cudaFuncAttributeMaxDynamicSharedMemorySize, SMEM_BYTES);
    edge_kernel<<<N_EDGES / (128 * NB), 256, SMEM_BYTES>>>(
        edge_feats, edge_attrs, charges_induced, eidx, out);
}